// round 6
// baseline (speedup 1.0000x reference)
#include <cuda_runtime.h>
#include <cuda_bf16.h>
#include <math.h>
#include <stdint.h>

#define BB 16
#define SS 128
#define VV 40000
#define DD 768
#define HH 12
#define HD 64
#define FF 3072
#define LL 12

typedef __nv_bfloat16 bf16;

// ---------------- fp32 scratch ----------------
__device__ float g_h   [BB*SS*DD];
__device__ float g_qkv [BB*SS*3*DD];
__device__ float g_proj[BB*SS*DD];
__device__ float g_ff2 [BB*SS*DD];
__device__ float g_bqkv[LL*3*DD];

// ---------------- bf16 split weights [N][K] ----------------
__device__ bf16 s_wqkv[2][LL*3*DD*DD];
__device__ bf16 s_wo  [2][LL*DD*DD];
__device__ bf16 s_w1  [2][LL*DD*FF];
__device__ bf16 s_w2  [2][LL*FF*DD];
__device__ bf16 s_wout[2][VV*DD];
__device__ bf16 s_actA[2][BB*SS*FF];
__device__ bf16 s_actB[2][BB*SS*FF];

// ======================= helpers =======================
__device__ __forceinline__ uint32_t smem_u32(const void* p) {
    uint32_t a;
    asm("{ .reg .u64 t; cvta.to.shared.u64 t, %1; cvt.u32.u64 %0, t; }" : "=r"(a) : "l"(p));
    return a;
}
__device__ __forceinline__ void cp16(uint32_t dst, const void* src) {
    asm volatile("cp.async.cg.shared.global [%0], [%1], 16;" :: "r"(dst), "l"(src) : "memory");
}
__device__ __forceinline__ void zero16(uint32_t dst) {
    asm volatile("st.shared.v4.b32 [%0], {%1,%1,%1,%1};" :: "r"(dst), "r"(0u) : "memory");
}
__device__ __forceinline__ void cp_commit() {
    asm volatile("cp.async.commit_group;" ::: "memory");
}
__device__ __forceinline__ void ldm4(uint32_t addr, uint32_t* r) {
    asm volatile("ldmatrix.sync.aligned.m8n8.x4.shared.b16 {%0,%1,%2,%3}, [%4];"
                 : "=r"(r[0]), "=r"(r[1]), "=r"(r[2]), "=r"(r[3]) : "r"(addr));
}
__device__ __forceinline__ void mma16816(float* d, const uint32_t* a, uint32_t b0, uint32_t b1) {
    asm volatile(
        "mma.sync.aligned.m16n8k16.row.col.f32.bf16.bf16.f32 "
        "{%0,%1,%2,%3}, {%4,%5,%6,%7}, {%8,%9}, {%0,%1,%2,%3};"
        : "+f"(d[0]), "+f"(d[1]), "+f"(d[2]), "+f"(d[3])
        : "r"(a[0]), "r"(a[1]), "r"(a[2]), "r"(a[3]), "r"(b0), "r"(b1));
}
__device__ __forceinline__ void split_bf16(float v, bf16& h, bf16& l) {
    h = __float2bfloat16(v);
    l = __float2bfloat16(v - __bfloat162float(h));
}

#define TROW 80

// ======================= small kernels =======================
__global__ void embed_kernel(const int* __restrict__ x,
                             const float* __restrict__ bpe,
                             const float* __restrict__ pe,
                             bf16* __restrict__ ah, bf16* __restrict__ al) {
    int idx = blockIdx.x * blockDim.x + threadIdx.x;
    if (idx >= BB*SS*DD) return;
    int d  = idx % DD;
    int bs = idx / DD;
    int s  = bs % SS;
    int tok = x[bs];
    float v = bpe[(long)tok*DD + d] + pe[s*DD + d];
    g_h[idx] = v;
    bf16 h, l; split_bf16(v, h, l);
    ah[idx] = h; al[idx] = l;
}

__global__ void concat_bias(const float* __restrict__ bq, const float* __restrict__ bk,
                            const float* __restrict__ bv) {
    int idx = blockIdx.x * blockDim.x + threadIdx.x;
    if (idx >= LL*3*DD) return;
    int l = idx / (3*DD), n = idx % (3*DD);
    float v;
    if (n < DD)          v = bq[l*DD + n];
    else if (n < 2*DD)   v = bk[l*DD + n - DD];
    else                 v = bv[l*DD + n - 2*DD];
    g_bqkv[idx] = v;
}

__global__ void conv_transpose(const float* __restrict__ src, bf16* __restrict__ dhi,
                               bf16* __restrict__ dlo, int R, int C,
                               long srcZ, int Z2, long dstZ1, long dstZ2) {
    __shared__ float t[32][33];
    int c0 = blockIdx.x * 32, r0 = blockIdx.y * 32;
    long zs = (long)blockIdx.z * srcZ;
    long zd = (long)(blockIdx.z / Z2) * dstZ1 + (long)(blockIdx.z % Z2) * dstZ2;
    int tx = threadIdx.x, ty = threadIdx.y;   // (16,16)
    #pragma unroll
    for (int i = 0; i < 2; i++) {
        int r = ty + i * 16;
        float2 v = *reinterpret_cast<const float2*>(&src[zs + (long)(r0 + r) * C + c0 + tx*2]);
        t[tx*2][r] = v.x;
        t[tx*2+1][r] = v.y;
    }
    __syncthreads();
    #pragma unroll
    for (int i = 0; i < 2; i++) {
        int cc = ty + i * 16;
        float a0 = t[cc][tx*2], a1 = t[cc][tx*2+1];
        bf16 h0, l0, h1, l1;
        split_bf16(a0, h0, l0);
        split_bf16(a1, h1, l1);
        long o = zd + (long)(c0 + cc) * R + r0 + tx*2;
        *reinterpret_cast<__nv_bfloat162*>(&dhi[o]) = __nv_bfloat162(h0, h1);
        *reinterpret_cast<__nv_bfloat162*>(&dlo[o]) = __nv_bfloat162(l0, l1);
    }
}

// ======================= gemm512: 128x256 tile, 512 thr, 3-stage =======================
// stage layout: Ah@0 (128*80), Al@10240, Bh@20480 (256*80), Bl@40960 ; stage=61440
#define S5_AH 0
#define S5_AL 10240
#define S5_BH 20480
#define S5_BL 40960
#define S5_STAGE 61440
#define S5_SMEM (3*S5_STAGE)

__device__ __forceinline__ void load512(
    uint32_t bb, const bf16* __restrict__ Ah, const bf16* __restrict__ Al,
    const bf16* __restrict__ Bh, const bf16* __restrict__ Bl,
    int m0, int n0, int N, int K, int c, int tid)
{
    int k0 = c << 5;
    {
        int row = tid >> 2, kq = tid & 3;       // 128 rows x 4 quads
        uint32_t doff = (uint32_t)(row * TROW + kq * 16);
        long aoff = (long)(m0 + row) * K + k0 + kq * 8;
        cp16(bb + S5_AH + doff, Ah + aoff);
        cp16(bb + S5_AL + doff, Al + aoff);
    }
    #pragma unroll
    for (int i = 0; i < 2; i++) {
        int ci = tid + i * 512;                  // 256 rows x 4 quads
        int row = ci >> 2, kq = ci & 3;
        uint32_t doff = (uint32_t)(row * TROW + kq * 16);
        int nr = n0 + row;
        if (nr < N) {
            long boff = (long)nr * K + k0 + kq * 8;
            cp16(bb + S5_BH + doff, Bh + boff);
            cp16(bb + S5_BL + doff, Bl + boff);
        } else {
            zero16(bb + S5_BH + doff);
            zero16(bb + S5_BL + doff);
        }
    }
}

template<int OUT>
__global__ __launch_bounds__(512, 1) void gemm512(
    const bf16* __restrict__ Ah, const bf16* __restrict__ Al,
    const bf16* __restrict__ Bh, const bf16* __restrict__ Bl,
    const float* __restrict__ bias, float* __restrict__ C,
    bf16* __restrict__ Oh, bf16* __restrict__ Ol,
    int N, int K)
{
    extern __shared__ char smem[];
    const uint32_t base = smem_u32(smem);
    const int tid  = threadIdx.x;
    const int lane = tid & 31;
    const int w    = tid >> 5;        // 0..15
    const int wm   = w & 3;           // 4 m-slots of 32
    const int wn   = w >> 2;          // 4 n-slots of 64
    const int m0 = blockIdx.x * 128, n0 = blockIdx.y * 256;
    const int nCh = K >> 5;

    float acc[2][8][4];
    #pragma unroll
    for (int i = 0; i < 2; i++)
        #pragma unroll
        for (int j = 0; j < 8; j++)
            #pragma unroll
            for (int q = 0; q < 4; q++) acc[i][j][q] = 0.f;

    const uint32_t a_loff = (uint32_t)((lane & 15) * TROW + ((lane >> 4) << 3) * 2);
    const uint32_t b_loff = (uint32_t)((((lane & 7) + ((lane & 16) ? 8 : 0)) * TROW) +
                                       ((lane & 8) ? 16 : 0));

    load512(base, Ah, Al, Bh, Bl, m0, n0, N, K, 0, tid);
    cp_commit();
    load512(base + S5_STAGE, Ah, Al, Bh, Bl, m0, n0, N, K, 1, tid);
    cp_commit();

    uint32_t sidx = 0;   // stage of chunk c
    for (int c = 0; c < nCh; c++) {
        if (c + 1 < nCh) {
            asm volatile("cp.async.wait_group 1;" ::: "memory");
        } else {
            asm volatile("cp.async.wait_group 0;" ::: "memory");
        }
        __syncthreads();

        uint32_t bb = base + sidx * S5_STAGE;
        uint32_t aH = bb + S5_AH + (uint32_t)(wm * 32) * TROW;
        uint32_t aL = bb + S5_AL + (uint32_t)(wm * 32) * TROW;
        uint32_t bH = bb + S5_BH + (uint32_t)(wn * 64) * TROW;
        uint32_t bL = bb + S5_BL + (uint32_t)(wn * 64) * TROW;

        #pragma unroll
        for (int ks = 0; ks < 2; ks++) {
            const uint32_t koff = (uint32_t)(ks * 32);
            uint32_t ah[2][4], al[2][4];
            #pragma unroll
            for (int mi = 0; mi < 2; mi++) {
                ldm4(aH + (uint32_t)(mi * 16) * TROW + a_loff + koff, ah[mi]);
                ldm4(aL + (uint32_t)(mi * 16) * TROW + a_loff + koff, al[mi]);
            }
            #pragma unroll
            for (int half = 0; half < 2; half++) {
                uint32_t bh[2][4], bl[2][4];
                #pragma unroll
                for (int g = 0; g < 2; g++) {
                    uint32_t go = (uint32_t)((half * 2 + g) * 16) * TROW;
                    ldm4(bH + go + b_loff + koff, bh[g]);
                    ldm4(bL + go + b_loff + koff, bl[g]);
                }
                #pragma unroll
                for (int mi = 0; mi < 2; mi++) {
                    #pragma unroll
                    for (int nj = 0; nj < 4; nj++) {
                        const int g = nj >> 1, o = (nj & 1) * 2;
                        float* a = acc[mi][half * 4 + nj];
                        mma16816(a, ah[mi], bh[g][o], bh[g][o + 1]);
                        mma16816(a, ah[mi], bl[g][o], bl[g][o + 1]);
                        mma16816(a, al[mi], bh[g][o], bh[g][o + 1]);
                    }
                }
            }
        }

        if (c + 2 < nCh) {
            uint32_t ns = (sidx + 2 >= 3) ? (sidx - 1) : (sidx + 2);
            load512(base + ns * S5_STAGE, Ah, Al, Bh, Bl, m0, n0, N, K, c + 2, tid);
            cp_commit();
        }
        sidx = (sidx + 1 == 3) ? 0 : sidx + 1;
    }

    // epilogue
    #pragma unroll
    for (int mi = 0; mi < 2; mi++) {
        int row = m0 + wm * 32 + mi * 16 + (lane >> 2);
        #pragma unroll
        for (int ni = 0; ni < 8; ni++) {
            int col = n0 + wn * 64 + ni * 8 + ((lane & 3) << 1);
            if (col < N) {
                float bx = bias[col], by = bias[col + 1];
                float v00 = acc[mi][ni][0] + bx, v01 = acc[mi][ni][1] + by;
                float v10 = acc[mi][ni][2] + bx, v11 = acc[mi][ni][3] + by;
                if (OUT == 0) {
                    *reinterpret_cast<float2*>(C + (long)row * N + col)       = make_float2(v00, v01);
                    *reinterpret_cast<float2*>(C + (long)(row + 8) * N + col) = make_float2(v10, v11);
                } else {
                    bf16 h0,l0,h1,l1,h2,l2,h3,l3;
                    split_bf16(v00, h0, l0); split_bf16(v01, h1, l1);
                    split_bf16(v10, h2, l2); split_bf16(v11, h3, l3);
                    *reinterpret_cast<__nv_bfloat162*>(Oh + (long)row * N + col)       = __nv_bfloat162(h0, h1);
                    *reinterpret_cast<__nv_bfloat162*>(Ol + (long)row * N + col)       = __nv_bfloat162(l0, l1);
                    *reinterpret_cast<__nv_bfloat162*>(Oh + (long)(row + 8) * N + col) = __nv_bfloat162(h2, h3);
                    *reinterpret_cast<__nv_bfloat162*>(Ol + (long)(row + 8) * N + col) = __nv_bfloat162(l2, l3);
                }
            }
        }
    }
}

// ======================= gemm_hmma 64x128 (proj / FF2) =======================
__device__ __forceinline__ void load_chunk64(
    uint32_t base, const bf16* __restrict__ Ah, const bf16* __restrict__ Al,
    const bf16* __restrict__ Bh, const bf16* __restrict__ Bl,
    int m0, int n0, int N, int K, int c, int tid)
{
    const uint32_t A_BYTES = 64 * TROW;
    const uint32_t BUF = (2 * 64 + 256) * TROW;
    uint32_t bb = base + (uint32_t)(c & 1) * BUF;
    int k0 = c << 5;
    {
        int row = tid >> 2, kq = tid & 3;
        if (row < 64) {
            uint32_t doff = (uint32_t)(row * TROW + kq * 16);
            long aoff = (long)(m0 + row) * K + k0 + kq * 8;
            cp16(bb + doff, Ah + aoff);
            cp16(bb + A_BYTES + doff, Al + aoff);
        }
    }
    #pragma unroll
    for (int i = 0; i < 2; i++) {
        int ci  = tid + i * 256;
        int row = ci >> 2, kq = ci & 3;
        uint32_t doff = (uint32_t)(row * TROW + kq * 16);
        int nr = n0 + row;
        if (nr < N) {
            long boff = (long)nr * K + k0 + kq * 8;
            cp16(bb + 2*A_BYTES + doff, Bh + boff);
            cp16(bb + 2*A_BYTES + 128*TROW + doff, Bl + boff);
        } else {
            zero16(bb + 2*A_BYTES + doff);
            zero16(bb + 2*A_BYTES + 128*TROW + doff);
        }
    }
}

__global__ __launch_bounds__(256, 2) void gemm_hmma64(
    const bf16* __restrict__ Ah, const bf16* __restrict__ Al,
    const bf16* __restrict__ Bh, const bf16* __restrict__ Bl,
    const float* __restrict__ bias, float* __restrict__ C,
    int N, int K)
{
    const uint32_t A_BYTES = 64 * TROW;
    const uint32_t BUF = (2 * 64 + 256) * TROW;
    extern __shared__ char smem[];
    const uint32_t base = smem_u32(smem);
    const int tid  = threadIdx.x;
    const int lane = tid & 31;
    const int w    = tid >> 5;
    const int wm   = w & 1;
    const int wn   = w >> 1;
    const int m0 = blockIdx.x * 64, n0 = blockIdx.y * 128;
    const int nCh = K >> 5;

    float acc[2][4][4];
    #pragma unroll
    for (int i = 0; i < 2; i++)
        #pragma unroll
        for (int j = 0; j < 4; j++)
            #pragma unroll
            for (int q = 0; q < 4; q++) acc[i][j][q] = 0.f;

    const uint32_t a_loff = (uint32_t)((lane & 15) * TROW + ((lane >> 4) << 3) * 2);
    const uint32_t b_loff = (uint32_t)((((lane & 7) + ((lane & 16) ? 8 : 0)) * TROW) +
                                       ((lane & 8) ? 16 : 0));

    load_chunk64(base, Ah, Al, Bh, Bl, m0, n0, N, K, 0, tid);
    cp_commit();

    for (int c = 0; c < nCh; c++) {
        if (c + 1 < nCh) {
            load_chunk64(base, Ah, Al, Bh, Bl, m0, n0, N, K, c + 1, tid);
            cp_commit();
            asm volatile("cp.async.wait_group 1;" ::: "memory");
        } else {
            asm volatile("cp.async.wait_group 0;" ::: "memory");
        }
        __syncthreads();

        uint32_t bb = base + (uint32_t)(c & 1) * BUF;
        uint32_t aH = bb + (uint32_t)(wm * 32) * TROW;
        uint32_t aL = aH + A_BYTES;
        uint32_t bH = bb + 2 * A_BYTES + (uint32_t)(wn * 32) * TROW;
        uint32_t bL = bH + 128 * TROW;

        #pragma unroll
        for (int ks = 0; ks < 2; ks++) {
            const uint32_t koff = (uint32_t)(ks * 32);
            uint32_t bh[2][4], bl[2][4];
            #pragma unroll
            for (int g = 0; g < 2; g++) {
                ldm4(bH + (uint32_t)(g * 16) * TROW + b_loff + koff, bh[g]);
                ldm4(bL + (uint32_t)(g * 16) * TROW + b_loff + koff, bl[g]);
            }
            #pragma unroll
            for (int mi = 0; mi < 2; mi++) {
                uint32_t ah[4], al[4];
                ldm4(aH + (uint32_t)(mi * 16) * TROW + a_loff + koff, ah);
                ldm4(aL + (uint32_t)(mi * 16) * TROW + a_loff + koff, al);
                #pragma unroll
                for (int ni = 0; ni < 4; ni++) {
                    const int g = ni >> 1, o = (ni & 1) * 2;
                    mma16816(acc[mi][ni], ah, bh[g][o], bh[g][o + 1]);
                    mma16816(acc[mi][ni], ah, bl[g][o], bl[g][o + 1]);
                    mma16816(acc[mi][ni], al, bh[g][o], bh[g][o + 1]);
                }
            }
        }
        __syncthreads();
    }

    #pragma unroll
    for (int mi = 0; mi < 2; mi++) {
        int row = m0 + wm * 32 + mi * 16 + (lane >> 2);
        #pragma unroll
        for (int ni = 0; ni < 4; ni++) {
            int col = n0 + wn * 32 + ni * 8 + ((lane & 3) << 1);
            if (col < N) {
                float bx = bias[col], by = bias[col + 1];
                *reinterpret_cast<float2*>(C + (long)row * N + col) =
                    make_float2(acc[mi][ni][0] + bx, acc[mi][ni][1] + by);
                *reinterpret_cast<float2*>(C + (long)(row + 8) * N + col) =
                    make_float2(acc[mi][ni][2] + bx, acc[mi][ni][3] + by);
            }
        }
    }
}

// ======================= attention =======================
__global__ __launch_bounds__(128) void attn_kernel(const int* __restrict__ ignore,
                                                   bf16* __restrict__ oh,
                                                   bf16* __restrict__ ol) {
    const int qi = blockIdx.x & (SS - 1);
    const int h  = (blockIdx.x >> 7) % HH;
    const int b  = blockIdx.x / (SS * HH);
    const int t  = threadIdx.x;
    const int QW = 3 * DD;

    __shared__ float qrow[HD];
    __shared__ float p[SS];
    __shared__ float red[SS];

    const float* qptr = g_qkv + ((long)(b * SS + qi) * QW + h * HD);
    if (t < HD) qrow[t] = qptr[t];
    __syncthreads();

    const bool allowed = (t <= qi) && (ignore[b * SS + t] == 0 || t == qi);
    float score = -INFINITY;
    if (allowed) {
        const float* kptr = g_qkv + ((long)(b * SS + t) * QW + DD + h * HD);
        float s = 0.f;
        #pragma unroll
        for (int e = 0; e < HD; e++) s += qrow[e] * kptr[e];
        score = s * 0.125f;
    }
    red[t] = score; __syncthreads();
    for (int off = 64; off > 0; off >>= 1) {
        if (t < off) red[t] = fmaxf(red[t], red[t + off]);
        __syncthreads();
    }
    const float mx = red[0];
    __syncthreads();
    const float e = allowed ? expf(score - mx) : 0.f;
    p[t] = e; red[t] = e; __syncthreads();
    for (int off = 64; off > 0; off >>= 1) {
        if (t < off) red[t] += red[t + off];
        __syncthreads();
    }
    const float inv = 1.f / red[0];
    if (t < HD) {
        const float* vbase = g_qkv + ((long)b * SS * QW + 2 * DD + h * HD + t);
        float o = 0.f;
        #pragma unroll 4
        for (int k = 0; k < SS; k++) o += p[k] * vbase[(long)k * QW];
        o *= inv;
        long oidx = (long)(b * SS + qi) * DD + h * HD + t;
        bf16 hh, ll; split_bf16(o, hh, ll);
        oh[oidx] = hh; ol[oidx] = ll;
    }
}

// ======================= residual (+GELU) + LayerNorm + split =======================
__global__ __launch_bounds__(256) void add_ln_kernel(
    const float* __restrict__ res_in,
    const float* __restrict__ w, const float* __restrict__ bvec,
    bf16* __restrict__ ah, bf16* __restrict__ al,
    int dogelu) {
    const int row = blockIdx.x;
    const int t = threadIdx.x;
    __shared__ float red[256];

    float vals[3];
    float sum = 0.f;
    #pragma unroll
    for (int i = 0; i < 3; i++) {
        int d = t + i * 256;
        float r = res_in[(long)row * DD + d];
        if (dogelu) r = 0.5f * r * (1.f + erff(r * 0.70710678118f));
        float v = g_h[(long)row * DD + d] + r;
        vals[i] = v;
        sum += v;
    }
    red[t] = sum; __syncthreads();
    for (int off = 128; off > 0; off >>= 1) {
        if (t < off) red[t] += red[t + off];
        __syncthreads();
    }
    const float mean = red[0] * (1.f / DD);
    __syncthreads();
    float vs = 0.f;
    #pragma unroll
    for (int i = 0; i < 3; i++) { float dv = vals[i] - mean; vs += dv * dv; }
    red[t] = vs; __syncthreads();
    for (int off = 128; off > 0; off >>= 1) {
        if (t < off) red[t] += red[t + off];
        __syncthreads();
    }
    const float rstd = rsqrtf(red[0] * (1.f / DD) + 1e-5f);
    #pragma unroll
    for (int i = 0; i < 3; i++) {
        int d = t + i * 256;
        float v = (vals[i] - mean) * rstd * w[d] + bvec[d];
        g_h[(long)row * DD + d] = v;
        bf16 hh, ll; split_bf16(v, hh, ll);
        ah[(long)row * DD + d] = hh;
        al[(long)row * DD + d] = ll;
    }
}

// ======================= host orchestration =======================
extern "C" void kernel_launch(void* const* d_in, const int* in_sizes, int n_in,
                              void* d_out, int out_size) {
    const int*   x    = (const int*)  d_in[0];
    const int*   ign  = (const int*)  d_in[1];
    const float* bpe  = (const float*)d_in[2];
    const float* pe   = (const float*)d_in[3];
    const float* Wq   = (const float*)d_in[4];
    const float* bq   = (const float*)d_in[5];
    const float* Wk   = (const float*)d_in[6];
    const float* bk   = (const float*)d_in[7];
    const float* Wv   = (const float*)d_in[8];
    const float* bv   = (const float*)d_in[9];
    const float* Wo   = (const float*)d_in[10];
    const float* bo   = (const float*)d_in[11];
    const float* W1   = (const float*)d_in[12];
    const float* b1   = (const float*)d_in[13];
    const float* W2   = (const float*)d_in[14];
    const float* b2   = (const float*)d_in[15];
    const float* ln1w = (const float*)d_in[16];
    const float* ln1b = (const float*)d_in[17];
    const float* ln2w = (const float*)d_in[18];
    const float* ln2b = (const float*)d_in[19];
    const float* Wout = (const float*)d_in[20];
    const float* bout = (const float*)d_in[21];
    float* out = (float*)d_out;

    float *gh, *gqkv, *gproj, *gff2, *gbqkv;
    cudaGetSymbolAddress((void**)&gh,    g_h);
    cudaGetSymbolAddress((void**)&gqkv,  g_qkv);
    cudaGetSymbolAddress((void**)&gproj, g_proj);
    cudaGetSymbolAddress((void**)&gff2,  g_ff2);
    cudaGetSymbolAddress((void**)&gbqkv, g_bqkv);

    bf16 *wqkv_h, *wo_h, *w1_h, *w2_h, *wout_h, *actA_h, *actB_h;
    bf16 *wqkv_l, *wo_l, *w1_l, *w2_l, *wout_l, *actA_l, *actB_l;
    void* p;
    cudaGetSymbolAddress(&p, s_wqkv); wqkv_h = (bf16*)p; wqkv_l = wqkv_h + (long)LL*3*DD*DD;
    cudaGetSymbolAddress(&p, s_wo);   wo_h = (bf16*)p;   wo_l   = wo_h   + (long)LL*DD*DD;
    cudaGetSymbolAddress(&p, s_w1);   w1_h = (bf16*)p;   w1_l   = w1_h   + (long)LL*DD*FF;
    cudaGetSymbolAddress(&p, s_w2);   w2_h = (bf16*)p;   w2_l   = w2_h   + (long)LL*FF*DD;
    cudaGetSymbolAddress(&p, s_wout); wout_h = (bf16*)p; wout_l = wout_h + (long)VV*DD;
    cudaGetSymbolAddress(&p, s_actA); actA_h = (bf16*)p; actA_l = actA_h + (long)BB*SS*FF;
    cudaGetSymbolAddress(&p, s_actB); actB_h = (bf16*)p; actB_l = actB_h + (long)BB*SS*FF;

    const int SM64 = (2*64 + 256) * TROW * 2;    // 61440
    cudaFuncSetAttribute(gemm512<0>, cudaFuncAttributeMaxDynamicSharedMemorySize, S5_SMEM);
    cudaFuncSetAttribute(gemm512<1>, cudaFuncAttributeMaxDynamicSharedMemorySize, S5_SMEM);
    cudaFuncSetAttribute(gemm_hmma64, cudaFuncAttributeMaxDynamicSharedMemorySize, SM64);

    const int M = BB * SS;  // 2048
    dim3 tb16(16, 16);

    // ---- weight conversion ----
    conv_transpose<<<dim3(HD/32, DD/32, LL*HH), tb16>>>(Wq, wqkv_h + 0L*DD*DD, wqkv_l + 0L*DD*DD,
        DD, HD, (long)DD*HD, HH, (long)3*DD*DD, (long)HD*DD);
    conv_transpose<<<dim3(HD/32, DD/32, LL*HH), tb16>>>(Wk, wqkv_h + 1L*DD*DD, wqkv_l + 1L*DD*DD,
        DD, HD, (long)DD*HD, HH, (long)3*DD*DD, (long)HD*DD);
    conv_transpose<<<dim3(HD/32, DD/32, LL*HH), tb16>>>(Wv, wqkv_h + 2L*DD*DD, wqkv_l + 2L*DD*DD,
        DD, HD, (long)DD*HD, HH, (long)3*DD*DD, (long)HD*DD);
    conv_transpose<<<dim3(DD/32, DD/32, LL), tb16>>>(Wo, wo_h, wo_l,
        DD, DD, (long)DD*DD, 1, (long)DD*DD, 0);
    conv_transpose<<<dim3(FF/32, DD/32, LL), tb16>>>(W1, w1_h, w1_l,
        DD, FF, (long)DD*FF, 1, (long)DD*FF, 0);
    conv_transpose<<<dim3(DD/32, FF/32, LL), tb16>>>(W2, w2_h, w2_l,
        FF, DD, (long)FF*DD, 1, (long)FF*DD, 0);
    conv_transpose<<<dim3(VV/32, DD/32, 1), tb16>>>(Wout, wout_h, wout_l,
        DD, VV, 0, 1, 0, 0);
    concat_bias<<<(LL*3*DD + 255)/256, 256>>>(bq, bk, bv);

    embed_kernel<<<(BB*SS*DD + 255)/256, 256>>>(x, bpe, pe, actA_h, actA_l);

    for (int l = 0; l < LL; l++) {
        gemm512<0><<<dim3(M/128, (3*DD)/256), 512, S5_SMEM>>>(actA_h, actA_l,
            wqkv_h + (long)l*3*DD*DD, wqkv_l + (long)l*3*DD*DD,
            gbqkv + (long)l*3*DD, gqkv, nullptr, nullptr, 3*DD, DD);

        attn_kernel<<<BB*HH*SS, 128>>>(ign, actB_h, actB_l);

        gemm_hmma64<<<dim3(M/64, DD/128), 256, SM64>>>(actB_h, actB_l,
            wo_h + (long)l*DD*DD, wo_l + (long)l*DD*DD,
            bo + (long)l*DD, gproj, DD, DD);
        add_ln_kernel<<<M, 256>>>(gproj, ln1w + (long)l*DD, ln1b + (long)l*DD,
                                  actA_h, actA_l, 0);

        gemm512<1><<<dim3(M/128, FF/256), 512, S5_SMEM>>>(actA_h, actA_l,
            w1_h + (long)l*DD*FF, w1_l + (long)l*DD*FF,
            b1 + (long)l*FF, nullptr, actB_h, actB_l, FF, DD);
        gemm_hmma64<<<dim3(M/64, DD/128), 256, SM64>>>(actB_h, actB_l,
            w2_h + (long)l*FF*DD, w2_l + (long)l*FF*DD,
            b2 + (long)l*DD, gff2, DD, FF);
        add_ln_kernel<<<M, 256>>>(gff2, ln2w + (long)l*DD, ln2b + (long)l*DD,
                                  actA_h, actA_l, 1);
    }

    gemm512<0><<<dim3(M/128, (VV + 255)/256), 512, S5_SMEM>>>(actA_h, actA_l,
        wout_h, wout_l, bout, out, nullptr, nullptr, VV, DD);
}